// round 5
// baseline (speedup 1.0000x reference)
#include <cuda_runtime.h>

#define B    2048
#define NC   32
#define M    496
#define H1   64
#define H2   32
#define CLS  10
#define EPS  1e-5f

__global__ __launch_bounds__(256) void nam_fused_kernel(
    const float* __restrict__ x,
    const float* __restrict__ W1, const float* __restrict__ b1,
    const float* __restrict__ g1, const float* __restrict__ be1,
    const float* __restrict__ m1, const float* __restrict__ v1,
    const float* __restrict__ W2, const float* __restrict__ b2,
    const float* __restrict__ g2, const float* __restrict__ be2,
    const float* __restrict__ m2, const float* __restrict__ v2,
    const float* __restrict__ W3, const float* __restrict__ b3,
    const float* __restrict__ Wout,
    float* __restrict__ out)
{
    const int m   = blockIdx.x;
    const int tid = threadIdx.x;
    const int b   = blockIdx.y * 256 + tid;

    __shared__ __align__(16) float  W2t[H1 * H2];  // [k][o] transposed
    __shared__ __align__(16) float4 ABCs[H1];      // folded layer-1 affine (A,B,C,-)
    __shared__ __align__(16) float4 DEWs[H2];      // folded BN2 (D,E) + W3
    __shared__ float wouts[CLS];                   // Wout[:, m]
    __shared__ float b3s;
    __shared__ int   sia, sib;

    // ---- stage weights for module m ----
    if (tid < H1) {
        const int o = tid;
        const float s = g1[m*H1 + o] * rsqrtf(v1[m*H1 + o] + EPS);
        ABCs[o] = make_float4(
            s * W1[(m*H1 + o)*2 + 0],
            s * W1[(m*H1 + o)*2 + 1],
            s * (b1[m*H1 + o] - m1[m*H1 + o]) + be1[m*H1 + o],
            0.0f);
    } else if (tid < H1 + H2) {
        const int o = tid - H1;
        const float s = g2[m*H2 + o] * rsqrtf(v2[m*H2 + o] + EPS);
        DEWs[o] = make_float4(
            s,
            s * (b2[m*H2 + o] - m2[m*H2 + o]) + be2[m*H2 + o],
            W3[m*H2 + o],
            0.0f);
    } else if (tid < H1 + H2 + CLS) {
        const int c = tid - (H1 + H2);
        wouts[c] = Wout[c * M + m];
    } else if (tid == H1 + H2 + CLS) {
        // m-th pair of combinations(range(32), 2), lexicographic
        int rem = m, i = 0;
        while (rem >= NC - 1 - i) { rem -= NC - 1 - i; i++; }
        sia = i;
        sib = i + 1 + rem;
        b3s = b3[m];
    }
    // Load W2[m] (H2 x H1, k fastest) transposed into smem as [k][o]
    #pragma unroll
    for (int r = 0; r < (H1 * H2) / 256; r++) {
        const int idx = tid + r * 256;
        const int o = idx / H1;
        const int k = idx % H1;
        W2t[k * H2 + o] = W2[m * (H2 * H1) + idx];
    }
    __syncthreads();

    const float xa = __ldg(&x[b * NC + sia]);
    const float xb = __ldg(&x[b * NC + sib]);

    float acc[H2];
    #pragma unroll
    for (int o = 0; o < H2; o++) acc[o] = 0.0f;

    #pragma unroll 4
    for (int k = 0; k < H1; k++) {
        const float4 abc = ABCs[k];
        const float h1k = fmaxf(fmaf(abc.x, xa, fmaf(abc.y, xb, abc.z)), 0.0f);
        const float4* w4 = reinterpret_cast<const float4*>(&W2t[k * H2]);
        #pragma unroll
        for (int o4 = 0; o4 < H2 / 4; o4++) {
            const float4 w = w4[o4];
            acc[o4*4 + 0] = fmaf(w.x, h1k, acc[o4*4 + 0]);
            acc[o4*4 + 1] = fmaf(w.y, h1k, acc[o4*4 + 1]);
            acc[o4*4 + 2] = fmaf(w.z, h1k, acc[o4*4 + 2]);
            acc[o4*4 + 3] = fmaf(w.w, h1k, acc[o4*4 + 3]);
        }
    }

    float res = b3s;
    #pragma unroll
    for (int o = 0; o < H2; o++) {
        const float4 dew = DEWs[o];
        res = fmaf(dew.z, fmaxf(fmaf(dew.x, acc[o], dew.y), 0.0f), res);
    }

    // ---- head contribution straight into out via no-return atomics ----
    #pragma unroll
    for (int c = 0; c < CLS; c++)
        atomicAdd(&out[b * CLS + c], res * wouts[c]);
}

// Initialize out[b][c] = bout[c] (out is poisoned by the harness).
__global__ __launch_bounds__(256) void head_init_kernel(
    const float* __restrict__ bout, float* __restrict__ out)
{
    const int i = blockIdx.x * 256 + threadIdx.x;
    if (i < B * CLS) out[i] = bout[i % CLS];
}

extern "C" void kernel_launch(void* const* d_in, const int* in_sizes, int n_in,
                              void* d_out, int out_size)
{
    // metadata order: x, pair_idx, W1, b1, g1, be1, m1, v1,
    //                 W2, b2, g2, be2, m2, v2, W3, b3, Wout, bout
    const float* x    = (const float*)d_in[0];
    // d_in[1] = pair_idx — intentionally unused (computed analytically on device)
    const float* W1   = (const float*)d_in[2];
    const float* b1   = (const float*)d_in[3];
    const float* g1   = (const float*)d_in[4];
    const float* be1  = (const float*)d_in[5];
    const float* m1   = (const float*)d_in[6];
    const float* v1   = (const float*)d_in[7];
    const float* W2   = (const float*)d_in[8];
    const float* b2   = (const float*)d_in[9];
    const float* g2   = (const float*)d_in[10];
    const float* be2  = (const float*)d_in[11];
    const float* m2   = (const float*)d_in[12];
    const float* v2   = (const float*)d_in[13];
    const float* W3   = (const float*)d_in[14];
    const float* b3   = (const float*)d_in[15];
    const float* Wout = (const float*)d_in[16];
    const float* bout = (const float*)d_in[17];
    float* out = (float*)d_out;

    head_init_kernel<<<(B * CLS + 255) / 256, 256>>>(bout, out);

    dim3 grid(M, B / 256);
    nam_fused_kernel<<<grid, 256>>>(x, W1, b1, g1, be1, m1, v1,
                                    W2, b2, g2, be2, m2, v2, W3, b3,
                                    Wout, out);
}

// round 7
// speedup vs baseline: 1.8906x; 1.8906x over previous
#include <cuda_runtime.h>

#define B    2048
#define NC   32
#define M    496
#define H1   64
#define H2   32
#define CLS  10
#define EPS  1e-5f
#define MSPLIT 16
#define MCHUNK (M / MSPLIT)    // 31

// Intermediate per-module outputs, transposed: g_ot[m*B + b]
__device__ float g_ot[M * B];

__global__ __launch_bounds__(256) void nam_modules_kernel(
    const float* __restrict__ x,
    const float* __restrict__ W1, const float* __restrict__ b1,
    const float* __restrict__ g1, const float* __restrict__ be1,
    const float* __restrict__ m1, const float* __restrict__ v1,
    const float* __restrict__ W2, const float* __restrict__ b2,
    const float* __restrict__ g2, const float* __restrict__ be2,
    const float* __restrict__ m2, const float* __restrict__ v2,
    const float* __restrict__ W3, const float* __restrict__ b3,
    const float* __restrict__ bout,
    float* __restrict__ out)
{
    const int m   = blockIdx.x;
    const int tid = threadIdx.x;
    const int b   = blockIdx.y * 256 + tid;

    // Fold out-init into this kernel (out is poisoned by the harness):
    // one column of blocks seeds out[b][:] = bout[:] before the head runs.
    if (blockIdx.x == 0) {
        #pragma unroll
        for (int c = 0; c < CLS; c++) out[b * CLS + c] = bout[c];
    }

    __shared__ __align__(16) float W2t[H1 * H2];   // [k][o] transposed
    __shared__ float As[H1], Bs[H1], Cs[H1];       // folded layer-1 affine (BN1 fused)
    __shared__ float Ds[H2], Es[H2], W3s[H2];      // folded BN2 + output weights
    __shared__ float b3s;
    __shared__ int   sia, sib;

    if (tid == 0) {
        // m-th pair of combinations(range(32), 2), lexicographic
        int rem = m, i = 0;
        while (rem >= NC - 1 - i) { rem -= NC - 1 - i; i++; }
        sia = i;
        sib = i + 1 + rem;
        b3s = b3[m];
    }
    if (tid < H1) {
        const int o = tid;
        const float s = g1[m*H1 + o] * rsqrtf(v1[m*H1 + o] + EPS);
        As[o] = s * W1[(m*H1 + o)*2 + 0];
        Bs[o] = s * W1[(m*H1 + o)*2 + 1];
        Cs[o] = s * (b1[m*H1 + o] - m1[m*H1 + o]) + be1[m*H1 + o];
    } else if (tid < H1 + H2) {
        const int o = tid - H1;
        const float s = g2[m*H2 + o] * rsqrtf(v2[m*H2 + o] + EPS);
        Ds[o]  = s;
        Es[o]  = s * (b2[m*H2 + o] - m2[m*H2 + o]) + be2[m*H2 + o];
        W3s[o] = W3[m*H2 + o];
    }
    // Load W2[m] (H2 x H1, k fastest) transposed into smem as [k][o]
    #pragma unroll
    for (int r = 0; r < (H1 * H2) / 256; r++) {
        const int idx = tid + r * 256;
        const int o = idx / H1;
        const int k = idx % H1;
        W2t[k * H2 + o] = W2[m * (H2 * H1) + idx];
    }
    __syncthreads();

    const float xa = x[b * NC + sia];
    const float xb = x[b * NC + sib];

    float acc[H2];
    #pragma unroll
    for (int o = 0; o < H2; o++) acc[o] = 0.0f;

    #pragma unroll 4
    for (int k = 0; k < H1; k++) {
        const float h1k = fmaxf(fmaf(As[k], xa, fmaf(Bs[k], xb, Cs[k])), 0.0f);
        const float4* w4 = reinterpret_cast<const float4*>(&W2t[k * H2]);
        #pragma unroll
        for (int o4 = 0; o4 < H2 / 4; o4++) {
            const float4 w = w4[o4];
            acc[o4*4 + 0] = fmaf(w.x, h1k, acc[o4*4 + 0]);
            acc[o4*4 + 1] = fmaf(w.y, h1k, acc[o4*4 + 1]);
            acc[o4*4 + 2] = fmaf(w.z, h1k, acc[o4*4 + 2]);
            acc[o4*4 + 3] = fmaf(w.w, h1k, acc[o4*4 + 3]);
        }
    }

    float res = b3s;
    #pragma unroll
    for (int o = 0; o < H2; o++)
        res += W3s[o] * fmaxf(fmaf(Ds[o], acc[o], Es[o]), 0.0f);

    g_ot[m * B + b] = res;
}

// Head: grid (B/256, MSPLIT). Thread = one b; reads 31 g values once each,
// accumulates all 10 classes in registers, then 10 low-duplication atomics.
__global__ __launch_bounds__(256) void nam_head_kernel(
    const float* __restrict__ Wout,   // [CLS, M]
    float* __restrict__ out)          // [B, CLS]
{
    const int tid = threadIdx.x;
    const int b   = blockIdx.x * 256 + tid;
    const int m0  = blockIdx.y * MCHUNK;

    __shared__ float ws[MCHUNK * CLS];   // ws[j][c] = Wout[c][m0+j]
    for (int i = tid; i < MCHUNK * CLS; i += 256) {   // 310 entries > 256 threads!
        const int j = i / CLS;
        const int c = i % CLS;
        ws[i] = Wout[c * M + m0 + j];
    }
    __syncthreads();

    float acc[CLS];
    #pragma unroll
    for (int c = 0; c < CLS; c++) acc[c] = 0.0f;

    const float* __restrict__ gcol = g_ot + m0 * B + b;
    #pragma unroll
    for (int j = 0; j < MCHUNK; j++) {
        const float g = gcol[j * B];             // coalesced LDG
        #pragma unroll
        for (int c = 0; c < CLS; c++)
            acc[c] = fmaf(g, ws[j * CLS + c], acc[c]);   // smem broadcast
    }

    #pragma unroll
    for (int c = 0; c < CLS; c++)
        atomicAdd(&out[b * CLS + c], acc[c]);
}

extern "C" void kernel_launch(void* const* d_in, const int* in_sizes, int n_in,
                              void* d_out, int out_size)
{
    // metadata order: x, pair_idx, W1, b1, g1, be1, m1, v1,
    //                 W2, b2, g2, be2, m2, v2, W3, b3, Wout, bout
    const float* x    = (const float*)d_in[0];
    // d_in[1] = pair_idx — intentionally unused (computed analytically on device)
    const float* W1   = (const float*)d_in[2];
    const float* b1   = (const float*)d_in[3];
    const float* g1   = (const float*)d_in[4];
    const float* be1  = (const float*)d_in[5];
    const float* m1   = (const float*)d_in[6];
    const float* v1   = (const float*)d_in[7];
    const float* W2   = (const float*)d_in[8];
    const float* b2   = (const float*)d_in[9];
    const float* g2   = (const float*)d_in[10];
    const float* be2  = (const float*)d_in[11];
    const float* m2   = (const float*)d_in[12];
    const float* v2   = (const float*)d_in[13];
    const float* W3   = (const float*)d_in[14];
    const float* b3   = (const float*)d_in[15];
    const float* Wout = (const float*)d_in[16];
    const float* bout = (const float*)d_in[17];
    float* out = (float*)d_out;

    dim3 grid1(M, B / 256);
    nam_modules_kernel<<<grid1, 256>>>(x, W1, b1, g1, be1, m1, v1,
                                       W2, b2, g2, be2, m2, v2, W3, b3,
                                       bout, out);

    dim3 grid2(B / 256, MSPLIT);
    nam_head_kernel<<<grid2, 256>>>(Wout, out);
}

// round 9
// speedup vs baseline: 2.9465x; 1.5585x over previous
#include <cuda_runtime.h>
#include <cuda_bf16.h>
#include <cstdint>

#define B    2048
#define NC   32
#define M    496
#define H1   64
#define H2   32
#define CLS  10
#define EPS  1e-5f
#define MPB  16                // modules per block
#define NMC  (M / MPB)         // 31 module-chunks
#define BT   128               // batch rows per block

// Row stride 144B (36 words): frag LDS bank = (4*row + tig) % 32 -> conflict-free
#define WSTR 36

// ---- smem layout (bytes / words) ----
#define AHI_B 0                //  128 rows * 144B = 18432
#define ALO_B 18432
#define BHI_B 36864            //   32 rows * 144B = 4608
#define BLO_B 41472
#define ABC_B 46080            //   64 * float4
#define DEW_B 47104            //   32 * float4
#define WOUT_B 47616           //   10 floats
#define B3_B  47656
#define SIA_B 47660
#define SIB_B 47664
#define SMEM_SZ 47668          //  < 48KB static limit

#define AHI_W (AHI_B/4)
#define ALO_W (ALO_B/4)
#define BHI_W (BHI_B/4)
#define BLO_W (BLO_B/4)

// Head partials: g_part[chunk][b][c]
__device__ float g_part[NMC * B * CLS];

static __device__ __forceinline__ uint32_t pack_bf16x2(float a, float b) {
    return (uint32_t)__bfloat16_as_ushort(__float2bfloat16(a)) |
           ((uint32_t)__bfloat16_as_ushort(__float2bfloat16(b)) << 16);
}

static __device__ __forceinline__ void mma16816(float c[4],
    uint32_t a0, uint32_t a1, uint32_t a2, uint32_t a3,
    uint32_t b0, uint32_t b1)
{
    asm volatile(
        "mma.sync.aligned.m16n8k16.row.col.f32.bf16.bf16.f32 "
        "{%0,%1,%2,%3}, {%4,%5,%6,%7}, {%8,%9}, {%0,%1,%2,%3};"
        : "+f"(c[0]), "+f"(c[1]), "+f"(c[2]), "+f"(c[3])
        : "r"(a0), "r"(a1), "r"(a2), "r"(a3), "r"(b0), "r"(b1));
}

__global__ __launch_bounds__(256) void nam_mma_kernel(
    const float* __restrict__ x,
    const float* __restrict__ W1, const float* __restrict__ b1,
    const float* __restrict__ g1, const float* __restrict__ be1,
    const float* __restrict__ m1, const float* __restrict__ v1,
    const float* __restrict__ W2, const float* __restrict__ b2,
    const float* __restrict__ g2, const float* __restrict__ be2,
    const float* __restrict__ m2, const float* __restrict__ v2,
    const float* __restrict__ W3, const float* __restrict__ b3,
    const float* __restrict__ Wout)
{
    __shared__ __align__(16) unsigned char sm[SMEM_SZ];
    uint32_t* smw = (uint32_t*)sm;

    const int tid  = threadIdx.x;
    const int lane = tid & 31;
    const int w    = tid >> 5;          // warp 0..7 -> rows 16w..16w+15
    const int gid  = lane >> 2;         // 0..7
    const int tig  = lane & 3;          // 0..3
    const int yoff = blockIdx.y * BT;
    const int mc   = blockIdx.x;

    // Persistent head accumulators for this thread's two rows (valid on tig==0)
    float acc0[CLS], acc1[CLS];
    #pragma unroll
    for (int c = 0; c < CLS; c++) { acc0[c] = 0.0f; acc1[c] = 0.0f; }

    const int hrow = tid & 127;         // h1 row this thread computes
    const int kh   = tid >> 7;          // k half (0: k<32, 1: k>=32)
    const int bh   = yoff + hrow;

    for (int mi = 0; mi < MPB; mi++) {
        const int m = mc * MPB + mi;
        __syncthreads();   // previous iteration fully consumed smem

        // ---- stage folded scalars ----
        if (tid < H1) {
            const int o = tid;
            const float s = g1[m*H1 + o] * rsqrtf(v1[m*H1 + o] + EPS);
            ((float4*)(sm + ABC_B))[o] = make_float4(
                s * W1[(m*H1 + o)*2 + 0],
                s * W1[(m*H1 + o)*2 + 1],
                s * (b1[m*H1 + o] - m1[m*H1 + o]) + be1[m*H1 + o], 0.0f);
        } else if (tid < H1 + H2) {
            const int o = tid - H1;
            const float s = g2[m*H2 + o] * rsqrtf(v2[m*H2 + o] + EPS);
            ((float4*)(sm + DEW_B))[o] = make_float4(
                s, s * (b2[m*H2 + o] - m2[m*H2 + o]) + be2[m*H2 + o],
                W3[m*H2 + o], 0.0f);
        } else if (tid < H1 + H2 + CLS) {
            const int c = tid - (H1 + H2);
            ((float*)(sm + WOUT_B))[c] = Wout[c * M + m];
        } else if (tid == H1 + H2 + CLS) {
            int rem = m, i = 0;
            while (rem >= NC - 1 - i) { rem -= NC - 1 - i; i++; }
            *(int*)(sm + SIA_B) = i;
            *(int*)(sm + SIB_B) = i + 1 + rem;
            *(float*)(sm + B3_B) = b3[m];
        }

        // ---- W2 -> B tiles (bf16 hi/lo), row o, word index = k-pair ----
        const float2* w2p = (const float2*)(W2 + m * (H2 * H1));
        #pragma unroll
        for (int r = 0; r < 4; r++) {
            const int p  = tid + r * 256;     // 0..1023
            const int o  = p >> 5;
            const int pk = p & 31;
            const float2 wv = w2p[p];
            const float t0 = __bfloat162float(__float2bfloat16(wv.x));
            const float t1 = __bfloat162float(__float2bfloat16(wv.y));
            const int word = o * WSTR + pk;
            smw[BHI_W + word] = pack_bf16x2(wv.x, wv.y);
            smw[BLO_W + word] = pack_bf16x2(wv.x - t0, wv.y - t1);
        }
        __syncthreads();

        // ---- layer1 (fp32) -> A tiles (bf16 hi/lo); thread = (row, khalf) ----
        {
            const int sia = *(const int*)(sm + SIA_B);
            const int sib = *(const int*)(sm + SIB_B);
            const float xa = x[bh * NC + sia];
            const float xb = x[bh * NC + sib];
            const float4* ABC = (const float4*)(sm + ABC_B);
            #pragma unroll
            for (int q = 0; q < 4; q++) {            // 4 pairs per uint4 store
                uint32_t hi4[4], lo4[4];
                #pragma unroll
                for (int j = 0; j < 4; j++) {
                    const int k0 = 32*kh + 2*(4*q + j);
                    const float4 c0 = ABC[k0];
                    const float4 c1 = ABC[k0 + 1];
                    const float h0 = fmaxf(fmaf(c0.x, xa, fmaf(c0.y, xb, c0.z)), 0.0f);
                    const float h1 = fmaxf(fmaf(c1.x, xa, fmaf(c1.y, xb, c1.z)), 0.0f);
                    const float t0 = __bfloat162float(__float2bfloat16(h0));
                    const float t1 = __bfloat162float(__float2bfloat16(h1));
                    hi4[j] = pack_bf16x2(h0, h1);
                    lo4[j] = pack_bf16x2(h0 - t0, h1 - t1);
                }
                const int word = hrow * WSTR + 16*kh + 4*q;
                *((uint4*)(smw + AHI_W + word)) = make_uint4(hi4[0], hi4[1], hi4[2], hi4[3]);
                *((uint4*)(smw + ALO_W + word)) = make_uint4(lo4[0], lo4[1], lo4[2], lo4[3]);
            }
        }
        __syncthreads();

        // ---- MMA: warp w owns m16 tile rows [16w, 16w+16), n = 0..31 ----
        float cf[4][4];
        #pragma unroll
        for (int nt = 0; nt < 4; nt++)
            #pragma unroll
            for (int j = 0; j < 4; j++) cf[nt][j] = 0.0f;

        const int arow = (16*w + gid) * WSTR;
        #pragma unroll
        for (int ks = 0; ks < 4; ks++) {
            const int ko = 8*ks + tig;
            const uint32_t ah0 = smw[AHI_W + arow + ko];
            const uint32_t ah1 = smw[AHI_W + arow + 8*WSTR + ko];
            const uint32_t ah2 = smw[AHI_W + arow + ko + 4];
            const uint32_t ah3 = smw[AHI_W + arow + 8*WSTR + ko + 4];
            const uint32_t al0 = smw[ALO_W + arow + ko];
            const uint32_t al1 = smw[ALO_W + arow + 8*WSTR + ko];
            const uint32_t al2 = smw[ALO_W + arow + ko + 4];
            const uint32_t al3 = smw[ALO_W + arow + 8*WSTR + ko + 4];
            uint32_t bh0[4], bh1[4], bl0[4], bl1[4];
            #pragma unroll
            for (int nt = 0; nt < 4; nt++) {
                const int brow = (8*nt + gid) * WSTR;
                bh0[nt] = smw[BHI_W + brow + ko];
                bh1[nt] = smw[BHI_W + brow + ko + 4];
                bl0[nt] = smw[BLO_W + brow + ko];
                bl1[nt] = smw[BLO_W + brow + ko + 4];
            }
            #pragma unroll
            for (int nt = 0; nt < 4; nt++)
                mma16816(cf[nt], ah0, ah1, ah2, ah3, bh0[nt], bh1[nt]);
            #pragma unroll
            for (int nt = 0; nt < 4; nt++)
                mma16816(cf[nt], ah0, ah1, ah2, ah3, bl0[nt], bl1[nt]);
            #pragma unroll
            for (int nt = 0; nt < 4; nt++)
                mma16816(cf[nt], al0, al1, al2, al3, bh0[nt], bh1[nt]);
        }

        // ---- epilogue: BN2 + ReLU + W3, row-reduce, head accumulate ----
        const float4* DEW = (const float4*)(sm + DEW_B);
        float p0 = 0.0f, p1 = 0.0f;
        #pragma unroll
        for (int nt = 0; nt < 4; nt++) {
            const int n0 = 8*nt + 2*tig;
            const float4 d0 = DEW[n0];
            const float4 d1 = DEW[n0 + 1];
            p0 = fmaf(d0.z, fmaxf(fmaf(d0.x, cf[nt][0], d0.y), 0.0f), p0);
            p0 = fmaf(d1.z, fmaxf(fmaf(d1.x, cf[nt][1], d1.y), 0.0f), p0);
            p1 = fmaf(d0.z, fmaxf(fmaf(d0.x, cf[nt][2], d0.y), 0.0f), p1);
            p1 = fmaf(d1.z, fmaxf(fmaf(d1.x, cf[nt][3], d1.y), 0.0f), p1);
        }
        p0 += __shfl_xor_sync(0xffffffffu, p0, 1);
        p0 += __shfl_xor_sync(0xffffffffu, p0, 2);
        p1 += __shfl_xor_sync(0xffffffffu, p1, 1);
        p1 += __shfl_xor_sync(0xffffffffu, p1, 2);

        if (tig == 0) {
            const float b3s = *(const float*)(sm + B3_B);
            const float res0 = b3s + p0;     // row 16w + gid
            const float res1 = b3s + p1;     // row 16w + gid + 8
            const float* wo = (const float*)(sm + WOUT_B);
            #pragma unroll
            for (int c = 0; c < CLS; c++) {
                acc0[c] = fmaf(res0, wo[c], acc0[c]);
                acc1[c] = fmaf(res1, wo[c], acc1[c]);
            }
        }
    }

    if (tig == 0) {
        const int r0 = yoff + 16*w + gid;
        const int r1 = r0 + 8;
        #pragma unroll
        for (int c = 0; c < CLS; c++) {
            g_part[(mc * B + r0) * CLS + c] = acc0[c];
            g_part[(mc * B + r1) * CLS + c] = acc1[c];
        }
    }
}

// out[b][c] = bout[c] + sum_chunks g_part[s][b][c]
__global__ __launch_bounds__(256) void nam_reduce_kernel(
    const float* __restrict__ bout, float* __restrict__ out)
{
    const int i = blockIdx.x * 256 + threadIdx.x;
    if (i >= B * CLS) return;
    float s = bout[i % CLS];
    #pragma unroll
    for (int mc = 0; mc < NMC; mc++)
        s += g_part[mc * (B * CLS) + i];
    out[i] = s;
}

extern "C" void kernel_launch(void* const* d_in, const int* in_sizes, int n_in,
                              void* d_out, int out_size)
{
    // metadata order: x, pair_idx, W1, b1, g1, be1, m1, v1,
    //                 W2, b2, g2, be2, m2, v2, W3, b3, Wout, bout
    const float* x    = (const float*)d_in[0];
    // d_in[1] = pair_idx — intentionally unused (computed analytically on device)
    const float* W1   = (const float*)d_in[2];
    const float* b1   = (const float*)d_in[3];
    const float* g1   = (const float*)d_in[4];
    const float* be1  = (const float*)d_in[5];
    const float* m1   = (const float*)d_in[6];
    const float* v1   = (const float*)d_in[7];
    const float* W2   = (const float*)d_in[8];
    const float* b2   = (const float*)d_in[9];
    const float* g2   = (const float*)d_in[10];
    const float* be2  = (const float*)d_in[11];
    const float* m2   = (const float*)d_in[12];
    const float* v2   = (const float*)d_in[13];
    const float* W3   = (const float*)d_in[14];
    const float* b3   = (const float*)d_in[15];
    const float* Wout = (const float*)d_in[16];
    const float* bout = (const float*)d_in[17];
    float* out = (float*)d_out;

    dim3 grid(NMC, B / BT);   // (31, 16)
    nam_mma_kernel<<<grid, 256>>>(x, W1, b1, g1, be1, m1, v1,
                                  W2, b2, g2, be2, m2, v2, W3, b3, Wout);
    nam_reduce_kernel<<<(B * CLS + 255) / 256, 256>>>(bout, out);
}

// round 10
// speedup vs baseline: 3.1552x; 1.0708x over previous
#include <cuda_runtime.h>
#include <cuda_bf16.h>
#include <cstdint>

#define B    2048
#define NC   32
#define M    496
#define H1   64
#define H2   32
#define CLS  10
#define EPS  1e-5f
#define MPB  16                // modules per block
#define NMC  (M / MPB)         // 31 module-chunks
#define BT   128               // batch rows per block

#define WSTR 36                // A-tile row stride in words (conflict-free frags)

// ---- smem layout (bytes) ----
#define AHI_B 0                // 128 rows * 144B = 18432
#define ALO_B 18432
#define BF_B  36864            // B frag store: 32 units * 264B = 8448
#define ABC_B 45312            // 64 * float4
#define DEW_B 46336            // 32 * float4
#define WOUT_B 46848           // 10 floats
#define B3_B  46888
#define SMEM_SZ 46892

#define AHI_W (AHI_B/4)
#define ALO_W (ALO_B/4)

// Head partials: g_part[chunk][b][c]
__device__ float g_part[NMC * B * CLS];

static __device__ __forceinline__ uint32_t bf2(float hi, float lo) {
    uint32_t r;
    asm("cvt.rn.bf16x2.f32 %0, %1, %2;" : "=r"(r) : "f"(hi), "f"(lo));
    return r;   // {hi -> [31:16], lo -> [15:0]}
}

static __device__ __forceinline__ void mma16816(float c[4],
    uint32_t a0, uint32_t a1, uint32_t a2, uint32_t a3,
    uint32_t b0, uint32_t b1)
{
    asm volatile(
        "mma.sync.aligned.m16n8k16.row.col.f32.bf16.bf16.f32 "
        "{%0,%1,%2,%3}, {%4,%5,%6,%7}, {%8,%9}, {%0,%1,%2,%3};"
        : "+f"(c[0]), "+f"(c[1]), "+f"(c[2]), "+f"(c[3])
        : "r"(a0), "r"(a1), "r"(a2), "r"(a3), "r"(b0), "r"(b1));
}

static __device__ __forceinline__ void adv_pair(int& i, int& j) {
    if (++j == NC) { ++i; j = i + 1; }
}

__global__ __launch_bounds__(256) void nam_mma_kernel(
    const float* __restrict__ x,
    const float* __restrict__ W1, const float* __restrict__ b1,
    const float* __restrict__ g1, const float* __restrict__ be1,
    const float* __restrict__ m1, const float* __restrict__ v1,
    const float* __restrict__ W2, const float* __restrict__ b2,
    const float* __restrict__ g2, const float* __restrict__ be2,
    const float* __restrict__ m2, const float* __restrict__ v2,
    const float* __restrict__ W3, const float* __restrict__ b3,
    const float* __restrict__ Wout)
{
    __shared__ __align__(16) unsigned char sm[SMEM_SZ];
    uint32_t* smw = (uint32_t*)sm;

    const int tid  = threadIdx.x;
    const int lane = tid & 31;
    const int w    = tid >> 5;          // warp 0..7 -> rows 16w..16w+15
    const int gid  = lane >> 2;         // 0..7
    const int tig  = lane & 3;          // 0..3
    const int yoff = blockIdx.y * BT;
    const int mc   = blockIdx.x;
    const int m0   = mc * MPB;

    const int hrow = tid & 127;         // h1 row this thread computes
    const int kh   = tid >> 7;          // k half (0: k<32, 1: k>=32)
    const int bh   = yoff + hrow;

    float acc0[CLS], acc1[CLS];
    #pragma unroll
    for (int c = 0; c < CLS; c++) { acc0[c] = 0.0f; acc1[c] = 0.0f; }

    // ---- staging roles (prefetch registers) ----
    const bool rABC  = tid < H1;
    const bool rDEW  = tid >= H1 && tid < H1 + H2;
    const bool rWOUT = tid >= H1 + H2 && tid < H1 + H2 + CLS;
    const bool rB3   = tid == H1 + H2 + CLS;
    float2 pw[4];
    float  st[7];

    // pair indices for m0 (all threads, uniform)
    int ci = 0, cj;
    { int rem = m0, i = 0;
      while (rem >= NC - 1 - i) { rem -= NC - 1 - i; i++; }
      ci = i; cj = i + 1 + rem; }

    // prologue: issue loads for module m0
    {
        const float2* w2p = (const float2*)(W2 + m0 * (H2 * H1));
        #pragma unroll
        for (int r = 0; r < 4; r++) pw[r] = w2p[tid + r * 256];
        if (rABC) {
            const int o = tid;
            st[0] = g1[m0*H1 + o]; st[1] = v1[m0*H1 + o];
            st[2] = W1[(m0*H1 + o)*2]; st[3] = W1[(m0*H1 + o)*2 + 1];
            st[4] = b1[m0*H1 + o]; st[5] = m1[m0*H1 + o]; st[6] = be1[m0*H1 + o];
        } else if (rDEW) {
            const int o = tid - H1;
            st[0] = g2[m0*H2 + o]; st[1] = v2[m0*H2 + o];
            st[2] = b2[m0*H2 + o]; st[3] = m2[m0*H2 + o];
            st[4] = be2[m0*H2 + o]; st[5] = W3[m0*H2 + o];
        } else if (rWOUT) {
            st[0] = Wout[(tid - (H1 + H2)) * M + m0];
        } else if (rB3) {
            st[0] = b3[m0];
        }
    }
    float xa = x[bh * NC + ci];
    float xb = x[bh * NC + cj];

    for (int mi = 0; mi < MPB; mi++) {
        // ==== commit staged registers -> smem ====
        #pragma unroll
        for (int r = 0; r < 4; r++) {
            const int p  = tid + r * 256;     // pair index: o = p>>5, pk = p&31
            const int o  = p >> 5;
            const int pk = p & 31;
            const int ks   = pk >> 3;
            const int wtig = pk & 3;
            const int slot = (pk >> 2) & 1;
            const int nt   = o >> 3;
            const int go   = o & 7;
            const float2 wv = pw[r];
            const uint32_t hi = bf2(wv.y, wv.x);
            const float r0 = wv.x - __uint_as_float(hi << 16);
            const float r1 = wv.y - __uint_as_float(hi & 0xffff0000u);
            const uint32_t lo = bf2(r1, r0);
            const int elem = 8*go + 2*wtig + slot;
            smw[(BF_B/4) + ((ks*2 + 0)*4 + nt)*66 + elem] = hi;
            smw[(BF_B/4) + ((ks*2 + 1)*4 + nt)*66 + elem] = lo;
        }
        if (rABC) {
            const float s = st[0] * rsqrtf(st[1] + EPS);
            ((float4*)(sm + ABC_B))[tid] = make_float4(
                s * st[2], s * st[3], s * (st[4] - st[5]) + st[6], 0.0f);
        } else if (rDEW) {
            const float s = st[0] * rsqrtf(st[1] + EPS);
            ((float4*)(sm + DEW_B))[tid - H1] = make_float4(
                s, s * (st[2] - st[3]) + st[4], st[5], 0.0f);
        } else if (rWOUT) {
            ((float*)(sm + WOUT_B))[tid - (H1 + H2)] = st[0];
        } else if (rB3) {
            *(float*)(sm + B3_B) = st[0];
        }
        __syncthreads();   // smem staged (B frags, ABC, DEW, WOUT, b3)

        // ==== layer1 (fp32) -> A tiles (bf16 hi/lo) ====
        {
            const float4* ABC = (const float4*)(sm + ABC_B);
            #pragma unroll
            for (int q = 0; q < 4; q++) {
                uint32_t hi4[4], lo4[4];
                #pragma unroll
                for (int j = 0; j < 4; j++) {
                    const int k0 = 32*kh + 2*(4*q + j);
                    const float4 c0 = ABC[k0];
                    const float4 c1 = ABC[k0 + 1];
                    const float h0 = fmaxf(fmaf(c0.x, xa, fmaf(c0.y, xb, c0.z)), 0.0f);
                    const float h1 = fmaxf(fmaf(c1.x, xa, fmaf(c1.y, xb, c1.z)), 0.0f);
                    const uint32_t hi = bf2(h1, h0);
                    const float r0 = h0 - __uint_as_float(hi << 16);
                    const float r1 = h1 - __uint_as_float(hi & 0xffff0000u);
                    hi4[j] = hi;
                    lo4[j] = bf2(r1, r0);
                }
                const int word = hrow * WSTR + 16*kh + 4*q;
                *((uint4*)(smw + AHI_W + word)) = make_uint4(hi4[0], hi4[1], hi4[2], hi4[3]);
                *((uint4*)(smw + ALO_W + word)) = make_uint4(lo4[0], lo4[1], lo4[2], lo4[3]);
            }
        }

        // ==== prefetch module mi+1 (overlaps barrier + MMA below) ====
        float xan = 0.0f, xbn = 0.0f;
        if (mi + 1 < MPB) {
            const int mn = m0 + mi + 1;
            adv_pair(ci, cj);
            xan = x[bh * NC + ci];
            xbn = x[bh * NC + cj];
            const float2* w2p = (const float2*)(W2 + mn * (H2 * H1));
            #pragma unroll
            for (int r = 0; r < 4; r++) pw[r] = w2p[tid + r * 256];
            if (rABC) {
                const int o = tid;
                st[0] = g1[mn*H1 + o]; st[1] = v1[mn*H1 + o];
                st[2] = W1[(mn*H1 + o)*2]; st[3] = W1[(mn*H1 + o)*2 + 1];
                st[4] = b1[mn*H1 + o]; st[5] = m1[mn*H1 + o]; st[6] = be1[mn*H1 + o];
            } else if (rDEW) {
                const int o = tid - H1;
                st[0] = g2[mn*H2 + o]; st[1] = v2[mn*H2 + o];
                st[2] = b2[mn*H2 + o]; st[3] = m2[mn*H2 + o];
                st[4] = be2[mn*H2 + o]; st[5] = W3[mn*H2 + o];
            } else if (rWOUT) {
                st[0] = Wout[(tid - (H1 + H2)) * M + mn];
            } else if (rB3) {
                st[0] = b3[mn];
            }
        }
        __syncthreads();   // A tiles ready

        // ==== MMA: warp w owns rows [16w, 16w+16) ====
        float cf[4][4];
        #pragma unroll
        for (int nt = 0; nt < 4; nt++)
            #pragma unroll
            for (int j = 0; j < 4; j++) cf[nt][j] = 0.0f;

        const int arow = (16*w + gid) * WSTR;
        #pragma unroll
        for (int ks = 0; ks < 4; ks++) {
            const int ko = 8*ks + tig;
            const uint32_t ah0 = smw[AHI_W + arow + ko];
            const uint32_t ah1 = smw[AHI_W + arow + 8*WSTR + ko];
            const uint32_t ah2 = smw[AHI_W + arow + ko + 4];
            const uint32_t ah3 = smw[AHI_W + arow + 8*WSTR + ko + 4];
            const uint32_t al0 = smw[ALO_W + arow + ko];
            const uint32_t al1 = smw[ALO_W + arow + 8*WSTR + ko];
            const uint32_t al2 = smw[ALO_W + arow + ko + 4];
            const uint32_t al3 = smw[ALO_W + arow + 8*WSTR + ko + 4];
            uint2 bh[4], bl[4];
            #pragma unroll
            for (int nt = 0; nt < 4; nt++) {
                bh[nt] = *((const uint2*)(smw + (BF_B/4) + ((ks*2 + 0)*4 + nt)*66 + lane*2));
                bl[nt] = *((const uint2*)(smw + (BF_B/4) + ((ks*2 + 1)*4 + nt)*66 + lane*2));
            }
            #pragma unroll
            for (int nt = 0; nt < 4; nt++)
                mma16816(cf[nt], ah0, ah1, ah2, ah3, bh[nt].x, bh[nt].y);
            #pragma unroll
            for (int nt = 0; nt < 4; nt++)
                mma16816(cf[nt], ah0, ah1, ah2, ah3, bl[nt].x, bl[nt].y);
            #pragma unroll
            for (int nt = 0; nt < 4; nt++)
                mma16816(cf[nt], al0, al1, al2, al3, bh[nt].x, bh[nt].y);
        }

        // ==== epilogue: BN2 + ReLU + W3, row-reduce, head accumulate ====
        const float4* DEW = (const float4*)(sm + DEW_B);
        float p0 = 0.0f, p1 = 0.0f;
        #pragma unroll
        for (int nt = 0; nt < 4; nt++) {
            const int n0 = 8*nt + 2*tig;
            const float4 d0 = DEW[n0];
            const float4 d1 = DEW[n0 + 1];
            p0 = fmaf(d0.z, fmaxf(fmaf(d0.x, cf[nt][0], d0.y), 0.0f), p0);
            p0 = fmaf(d1.z, fmaxf(fmaf(d1.x, cf[nt][1], d1.y), 0.0f), p0);
            p1 = fmaf(d0.z, fmaxf(fmaf(d0.x, cf[nt][2], d0.y), 0.0f), p1);
            p1 = fmaf(d1.z, fmaxf(fmaf(d1.x, cf[nt][3], d1.y), 0.0f), p1);
        }
        p0 += __shfl_xor_sync(0xffffffffu, p0, 1);
        p0 += __shfl_xor_sync(0xffffffffu, p0, 2);
        p1 += __shfl_xor_sync(0xffffffffu, p1, 1);
        p1 += __shfl_xor_sync(0xffffffffu, p1, 2);

        if (tig == 0) {
            const float b3s = *(const float*)(sm + B3_B);
            const float res0 = b3s + p0;
            const float res1 = b3s + p1;
            const float* wo = (const float*)(sm + WOUT_B);
            #pragma unroll
            for (int c = 0; c < CLS; c++) {
                acc0[c] = fmaf(res0, wo[c], acc0[c]);
                acc1[c] = fmaf(res1, wo[c], acc1[c]);
            }
        }
        __syncthreads();   // all smem reads done before next commit overwrites

        xa = xan; xb = xbn;
    }

    if (tig == 0) {
        const int r0 = yoff + 16*w + gid;
        const int r1 = r0 + 8;
        #pragma unroll
        for (int c = 0; c < CLS; c++) {
            g_part[(mc * B + r0) * CLS + c] = acc0[c];
            g_part[(mc * B + r1) * CLS + c] = acc1[c];
        }
    }
}

// out[i2 pairs] = bout + sum_chunks g_part (float2-vectorized)
__global__ __launch_bounds__(256) void nam_reduce_kernel(
    const float* __restrict__ bout, float* __restrict__ out)
{
    const int i2 = blockIdx.x * 256 + threadIdx.x;   // 0 .. B*CLS/2-1
    if (i2 >= (B * CLS) / 2) return;
    const int i = i2 * 2;
    float2 s = make_float2(bout[i % CLS], bout[(i + 1) % CLS]);
    #pragma unroll
    for (int mc = 0; mc < NMC; mc++) {
        const float2 v = *((const float2*)(g_part + mc * (B * CLS) + i));
        s.x += v.x; s.y += v.y;
    }
    *((float2*)(out + i)) = s;
}

extern "C" void kernel_launch(void* const* d_in, const int* in_sizes, int n_in,
                              void* d_out, int out_size)
{
    // metadata order: x, pair_idx, W1, b1, g1, be1, m1, v1,
    //                 W2, b2, g2, be2, m2, v2, W3, b3, Wout, bout
    const float* x    = (const float*)d_in[0];
    // d_in[1] = pair_idx — intentionally unused (computed analytically on device)
    const float* W1   = (const float*)d_in[2];
    const float* b1   = (const float*)d_in[3];
    const float* g1   = (const float*)d_in[4];
    const float* be1  = (const float*)d_in[5];
    const float* m1   = (const float*)d_in[6];
    const float* v1   = (const float*)d_in[7];
    const float* W2   = (const float*)d_in[8];
    const float* b2   = (const float*)d_in[9];
    const float* g2   = (const float*)d_in[10];
    const float* be2  = (const float*)d_in[11];
    const float* m2   = (const float*)d_in[12];
    const float* v2   = (const float*)d_in[13];
    const float* W3   = (const float*)d_in[14];
    const float* b3   = (const float*)d_in[15];
    const float* Wout = (const float*)d_in[16];
    const float* bout = (const float*)d_in[17];
    float* out = (float*)d_out;

    dim3 grid(NMC, B / BT);   // (31, 16)
    nam_mma_kernel<<<grid, 256>>>(x, W1, b1, g1, be1, m1, v1,
                                  W2, b2, g2, be2, m2, v2, W3, b3, Wout);
    nam_reduce_kernel<<<(B * CLS / 2 + 255) / 256, 256>>>(bout, out);
}

// round 11
// speedup vs baseline: 3.9796x; 1.2613x over previous
#include <cuda_runtime.h>
#include <cuda_fp16.h>
#include <cstdint>

#define B    2048
#define NC   32
#define M    496
#define H1   64
#define H2   32
#define CLS  10
#define EPS  1e-5f
#define MPB  16                // modules per block
#define NMC  (M / MPB)         // 31 module-chunks
#define BT   128               // batch rows per block

#define WSTR 36                // A-tile row stride in words (conflict-free frags)

// ---- smem layout (bytes) ----
#define A_B   0                // 128 rows * 144B = 18432
#define BF_B  18432            // B frag store: 16 units * 264B = 4224
#define ABC_B 22656            // 64 * float4
#define DEW_B 23680            // 32 * float4
#define WOUT_B 24192           // 10 floats
#define B3_B  24232
#define SMEM_SZ 24236

#define A_W  (A_B/4)
#define BF_W (BF_B/4)

// Head partials: g_part[chunk][b][c]
__device__ float g_part[NMC * B * CLS];

static __device__ __forceinline__ uint32_t f16x2(float hi, float lo) {
    uint32_t r;
    asm("cvt.rn.f16x2.f32 %0, %1, %2;" : "=r"(r) : "f"(hi), "f"(lo));
    return r;   // hi -> [31:16], lo -> [15:0]
}

static __device__ __forceinline__ void mma16816(float c[4],
    uint32_t a0, uint32_t a1, uint32_t a2, uint32_t a3,
    uint32_t b0, uint32_t b1)
{
    asm volatile(
        "mma.sync.aligned.m16n8k16.row.col.f32.f16.f16.f32 "
        "{%0,%1,%2,%3}, {%4,%5,%6,%7}, {%8,%9}, {%0,%1,%2,%3};"
        : "+f"(c[0]), "+f"(c[1]), "+f"(c[2]), "+f"(c[3])
        : "r"(a0), "r"(a1), "r"(a2), "r"(a3), "r"(b0), "r"(b1));
}

static __device__ __forceinline__ void adv_pair(int& i, int& j) {
    if (++j == NC) { ++i; j = i + 1; }
}

__global__ __launch_bounds__(256) void nam_mma_kernel(
    const float* __restrict__ x,
    const float* __restrict__ W1, const float* __restrict__ b1,
    const float* __restrict__ g1, const float* __restrict__ be1,
    const float* __restrict__ m1, const float* __restrict__ v1,
    const float* __restrict__ W2, const float* __restrict__ b2,
    const float* __restrict__ g2, const float* __restrict__ be2,
    const float* __restrict__ m2, const float* __restrict__ v2,
    const float* __restrict__ W3, const float* __restrict__ b3,
    const float* __restrict__ Wout)
{
    __shared__ __align__(16) unsigned char sm[SMEM_SZ];
    uint32_t* smw = (uint32_t*)sm;

    const int tid  = threadIdx.x;
    const int lane = tid & 31;
    const int w    = tid >> 5;          // warp 0..7 -> rows 16w..16w+15
    const int gid  = lane >> 2;         // 0..7
    const int tig  = lane & 3;          // 0..3
    const int yoff = blockIdx.y * BT;
    const int mc   = blockIdx.x;
    const int m0   = mc * MPB;

    const int hrow = tid & 127;         // h1 row this thread computes
    const int kh   = tid >> 7;          // k half (0: k<32, 1: k>=32)
    const int bh   = yoff + hrow;

    float acc0[CLS], acc1[CLS];
    #pragma unroll
    for (int c = 0; c < CLS; c++) { acc0[c] = 0.0f; acc1[c] = 0.0f; }

    // ---- staging roles (prefetch registers) ----
    const bool rABC  = tid < H1;
    const bool rDEW  = tid >= H1 && tid < H1 + H2;
    const bool rWOUT = tid >= H1 + H2 && tid < H1 + H2 + CLS;
    const bool rB3   = tid == H1 + H2 + CLS;
    float2 pw[4];
    float  st[7];

    // pair indices for m0 (all threads, uniform)
    int ci = 0, cj;
    { int rem = m0, i = 0;
      while (rem >= NC - 1 - i) { rem -= NC - 1 - i; i++; }
      ci = i; cj = i + 1 + rem; }

    // prologue: issue loads for module m0
    {
        const float2* w2p = (const float2*)(W2 + m0 * (H2 * H1));
        #pragma unroll
        for (int r = 0; r < 4; r++) pw[r] = w2p[tid + r * 256];
        if (rABC) {
            const int o = tid;
            st[0] = g1[m0*H1 + o]; st[1] = v1[m0*H1 + o];
            st[2] = W1[(m0*H1 + o)*2]; st[3] = W1[(m0*H1 + o)*2 + 1];
            st[4] = b1[m0*H1 + o]; st[5] = m1[m0*H1 + o]; st[6] = be1[m0*H1 + o];
        } else if (rDEW) {
            const int o = tid - H1;
            st[0] = g2[m0*H2 + o]; st[1] = v2[m0*H2 + o];
            st[2] = b2[m0*H2 + o]; st[3] = m2[m0*H2 + o];
            st[4] = be2[m0*H2 + o]; st[5] = W3[m0*H2 + o];
        } else if (rWOUT) {
            st[0] = Wout[(tid - (H1 + H2)) * M + m0];
        } else if (rB3) {
            st[0] = b3[m0];
        }
    }
    float xa = x[bh * NC + ci];
    float xb = x[bh * NC + cj];

    for (int mi = 0; mi < MPB; mi++) {
        // ==== commit staged registers -> smem (fp16) ====
        #pragma unroll
        for (int r = 0; r < 4; r++) {
            const int p  = tid + r * 256;     // pair index: o = p>>5, pk = p&31
            const int o  = p >> 5;
            const int pk = p & 31;
            const int ks   = pk >> 3;
            const int wtig = pk & 3;
            const int slot = (pk >> 2) & 1;
            const int nt   = o >> 3;
            const int go   = o & 7;
            const float2 wv = pw[r];
            const int elem = 8*go + 2*wtig + slot;
            smw[BF_W + (ks*4 + nt)*66 + elem] = f16x2(wv.y, wv.x);
        }
        if (rABC) {
            const float s = st[0] * rsqrtf(st[1] + EPS);
            ((float4*)(sm + ABC_B))[tid] = make_float4(
                s * st[2], s * st[3], s * (st[4] - st[5]) + st[6], 0.0f);
        } else if (rDEW) {
            const float s = st[0] * rsqrtf(st[1] + EPS);
            ((float4*)(sm + DEW_B))[tid - H1] = make_float4(
                s, s * (st[2] - st[3]) + st[4], st[5], 0.0f);
        } else if (rWOUT) {
            ((float*)(sm + WOUT_B))[tid - (H1 + H2)] = st[0];
        } else if (rB3) {
            *(float*)(sm + B3_B) = st[0];
        }
        __syncthreads();   // smem staged (B frags, ABC, DEW, WOUT, b3)

        // ==== layer1 (fp32) -> A tile (fp16) ====
        {
            const float4* ABC = (const float4*)(sm + ABC_B);
            #pragma unroll
            for (int q = 0; q < 4; q++) {
                uint32_t w4[4];
                #pragma unroll
                for (int j = 0; j < 4; j++) {
                    const int k0 = 32*kh + 2*(4*q + j);
                    const float4 c0 = ABC[k0];
                    const float4 c1 = ABC[k0 + 1];
                    const float h0 = fmaxf(fmaf(c0.x, xa, fmaf(c0.y, xb, c0.z)), 0.0f);
                    const float h1 = fmaxf(fmaf(c1.x, xa, fmaf(c1.y, xb, c1.z)), 0.0f);
                    w4[j] = f16x2(h1, h0);
                }
                const int word = hrow * WSTR + 16*kh + 4*q;
                *((uint4*)(smw + A_W + word)) = make_uint4(w4[0], w4[1], w4[2], w4[3]);
            }
        }

        // ==== prefetch module mi+1 (overlaps barrier + MMA below) ====
        float xan = 0.0f, xbn = 0.0f;
        if (mi + 1 < MPB) {
            const int mn = m0 + mi + 1;
            adv_pair(ci, cj);
            xan = x[bh * NC + ci];
            xbn = x[bh * NC + cj];
            const float2* w2p = (const float2*)(W2 + mn * (H2 * H1));
            #pragma unroll
            for (int r = 0; r < 4; r++) pw[r] = w2p[tid + r * 256];
            if (rABC) {
                const int o = tid;
                st[0] = g1[mn*H1 + o]; st[1] = v1[mn*H1 + o];
                st[2] = W1[(mn*H1 + o)*2]; st[3] = W1[(mn*H1 + o)*2 + 1];
                st[4] = b1[mn*H1 + o]; st[5] = m1[mn*H1 + o]; st[6] = be1[mn*H1 + o];
            } else if (rDEW) {
                const int o = tid - H1;
                st[0] = g2[mn*H2 + o]; st[1] = v2[mn*H2 + o];
                st[2] = b2[mn*H2 + o]; st[3] = m2[mn*H2 + o];
                st[4] = be2[mn*H2 + o]; st[5] = W3[mn*H2 + o];
            } else if (rWOUT) {
                st[0] = Wout[(tid - (H1 + H2)) * M + mn];
            } else if (rB3) {
                st[0] = b3[mn];
            }
        }
        __syncthreads();   // A tile ready

        // ==== MMA: warp w owns rows [16w, 16w+16), 16 HMMA/module ====
        float cf[4][4];
        #pragma unroll
        for (int nt = 0; nt < 4; nt++)
            #pragma unroll
            for (int j = 0; j < 4; j++) cf[nt][j] = 0.0f;

        const int arow = (16*w + gid) * WSTR;
        #pragma unroll
        for (int ks = 0; ks < 4; ks++) {
            const int ko = 8*ks + tig;
            const uint32_t a0 = smw[A_W + arow + ko];
            const uint32_t a1 = smw[A_W + arow + 8*WSTR + ko];
            const uint32_t a2 = smw[A_W + arow + ko + 4];
            const uint32_t a3 = smw[A_W + arow + 8*WSTR + ko + 4];
            uint2 bf[4];
            #pragma unroll
            for (int nt = 0; nt < 4; nt++)
                bf[nt] = *((const uint2*)(smw + BF_W + (ks*4 + nt)*66 + lane*2));
            #pragma unroll
            for (int nt = 0; nt < 4; nt++)
                mma16816(cf[nt], a0, a1, a2, a3, bf[nt].x, bf[nt].y);
        }

        // ==== epilogue: BN2 + ReLU + W3, row-reduce, head accumulate ====
        const float4* DEW = (const float4*)(sm + DEW_B);
        float p0 = 0.0f, p1 = 0.0f;
        #pragma unroll
        for (int nt = 0; nt < 4; nt++) {
            const int n0 = 8*nt + 2*tig;
            const float4 d0 = DEW[n0];
            const float4 d1 = DEW[n0 + 1];
            p0 = fmaf(d0.z, fmaxf(fmaf(d0.x, cf[nt][0], d0.y), 0.0f), p0);
            p0 = fmaf(d1.z, fmaxf(fmaf(d1.x, cf[nt][1], d1.y), 0.0f), p0);
            p1 = fmaf(d0.z, fmaxf(fmaf(d0.x, cf[nt][2], d0.y), 0.0f), p1);
            p1 = fmaf(d1.z, fmaxf(fmaf(d1.x, cf[nt][3], d1.y), 0.0f), p1);
        }
        p0 += __shfl_xor_sync(0xffffffffu, p0, 1);
        p0 += __shfl_xor_sync(0xffffffffu, p0, 2);
        p1 += __shfl_xor_sync(0xffffffffu, p1, 1);
        p1 += __shfl_xor_sync(0xffffffffu, p1, 2);

        if (tig == 0) {
            const float b3s = *(const float*)(sm + B3_B);
            const float res0 = b3s + p0;
            const float res1 = b3s + p1;
            const float* wo = (const float*)(sm + WOUT_B);
            #pragma unroll
            for (int c = 0; c < CLS; c++) {
                acc0[c] = fmaf(res0, wo[c], acc0[c]);
                acc1[c] = fmaf(res1, wo[c], acc1[c]);
            }
        }
        __syncthreads();   // all smem reads done before next commit overwrites

        xa = xan; xb = xbn;
    }

    if (tig == 0) {
        const int r0 = yoff + 16*w + gid;
        const int r1 = r0 + 8;
        #pragma unroll
        for (int c = 0; c < CLS; c++) {
            g_part[(mc * B + r0) * CLS + c] = acc0[c];
            g_part[(mc * B + r1) * CLS + c] = acc1[c];
        }
    }
}

// out[i2 pairs] = bout + sum_chunks g_part (float2-vectorized)
__global__ __launch_bounds__(256) void nam_reduce_kernel(
    const float* __restrict__ bout, float* __restrict__ out)
{
    const int i2 = blockIdx.x * 256 + threadIdx.x;   // 0 .. B*CLS/2-1
    if (i2 >= (B * CLS) / 2) return;
    const int i = i2 * 2;
    float2 s = make_float2(bout[i % CLS], bout[(i + 1) % CLS]);
    #pragma unroll
    for (int mc = 0; mc < NMC; mc++) {
        const float2 v = *((const float2*)(g_part + mc * (B * CLS) + i));
        s.x += v.x; s.y += v.y;
    }
    *((float2*)(out + i)) = s;
}

extern "C" void kernel_launch(void* const* d_in, const int* in_sizes, int n_in,
                              void* d_out, int out_size)
{
    // metadata order: x, pair_idx, W1, b1, g1, be1, m1, v1,
    //                 W2, b2, g2, be2, m2, v2, W3, b3, Wout, bout
    const float* x    = (const float*)d_in[0];
    // d_in[1] = pair_idx — intentionally unused (computed analytically on device)
    const float* W1   = (const float*)d_in[2];
    const float* b1   = (const float*)d_in[3];
    const float* g1   = (const float*)d_in[4];
    const float* be1  = (const float*)d_in[5];
    const float* m1   = (const float*)d_in[6];
    const float* v1   = (const float*)d_in[7];
    const float* W2   = (const float*)d_in[8];
    const float* b2   = (const float*)d_in[9];
    const float* g2   = (const float*)d_in[10];
    const float* be2  = (const float*)d_in[11];
    const float* m2   = (const float*)d_in[12];
    const float* v2   = (const float*)d_in[13];
    const float* W3   = (const float*)d_in[14];
    const float* b3   = (const float*)d_in[15];
    const float* Wout = (const float*)d_in[16];
    const float* bout = (const float*)d_in[17];
    float* out = (float*)d_out;

    dim3 grid(NMC, B / BT);   // (31, 16)
    nam_mma_kernel<<<grid, 256>>>(x, W1, b1, g1, be1, m1, v1,
                                  W2, b2, g2, be2, m2, v2, W3, b3, Wout);
    nam_reduce_kernel<<<(B * CLS / 2 + 255) / 256, 256>>>(bout, out);
}